// round 12
// baseline (speedup 1.0000x reference)
#include <cuda_runtime.h>
#include <cuda_bf16.h>
#include <cuda_fp16.h>
#include <cstdint>

#define NPOS 4096
#define CH   256
#define BATCH 8
#define QT   128          // queries per CTA (attn)
#define KTILE 64          // keys per tile
#define NKT  (NPOS / KTILE)

// scratch
__device__ __align__(16) __nv_bfloat16 g_xb[BATCH * CH * NPOS];  // x bf16 (b,c,n)
__device__ __align__(16) __nv_bfloat16 g_wb[3 * CH * CH];        // W bf16 (m,o,c)
__device__ __align__(16) __nv_bfloat16 g_q[BATCH * NPOS * CH];   // (b,n,c)
__device__ __align__(16) __nv_bfloat16 g_k[BATCH * NPOS * CH];   // (b,n,c)
__device__ __align__(16) __half       g_v[BATCH * NPOS * CH];    // (b,n,c)  f16

// ---------------------------------------------------------------------------
// helpers
// ---------------------------------------------------------------------------
__device__ __forceinline__ uint32_t s2u(const void* p) {
    uint32_t a;
    asm("{ .reg .u64 t; cvta.to.shared.u64 t, %1; cvt.u32.u64 %0, t; }" : "=r"(a) : "l"(p));
    return a;
}
__device__ __forceinline__ void cpa16(uint32_t s, const void* g) {
    asm volatile("cp.async.cg.shared.global [%0], [%1], 16;" :: "r"(s), "l"(g));
}
__device__ __forceinline__ void cp_commit() { asm volatile("cp.async.commit_group;"); }
template <int N> __device__ __forceinline__ void cp_wait() {
    asm volatile("cp.async.wait_group %0;" :: "n"(N));
}
__device__ __forceinline__ void ldsm4(uint32_t* r, uint32_t a) {
    asm volatile("ldmatrix.sync.aligned.m8n8.x4.shared.b16 {%0,%1,%2,%3}, [%4];"
        : "=r"(r[0]), "=r"(r[1]), "=r"(r[2]), "=r"(r[3]) : "r"(a));
}
__device__ __forceinline__ void ldsm4t(uint32_t* r, uint32_t a) {
    asm volatile("ldmatrix.sync.aligned.m8n8.x4.trans.shared.b16 {%0,%1,%2,%3}, [%4];"
        : "=r"(r[0]), "=r"(r[1]), "=r"(r[2]), "=r"(r[3]) : "r"(a));
}
__device__ __forceinline__ void mma16816(float* d, const uint32_t* a, uint32_t b0, uint32_t b1) {
    asm volatile("mma.sync.aligned.m16n8k16.row.col.f32.bf16.bf16.f32 "
        "{%0,%1,%2,%3}, {%4,%5,%6,%7}, {%8,%9}, {%0,%1,%2,%3};"
        : "+f"(d[0]), "+f"(d[1]), "+f"(d[2]), "+f"(d[3])
        : "r"(a[0]), "r"(a[1]), "r"(a[2]), "r"(a[3]), "r"(b0), "r"(b1));
}
__device__ __forceinline__ void mma16816h(uint32_t* d, const uint32_t* a, uint32_t b0, uint32_t b1) {
    asm volatile("mma.sync.aligned.m16n8k16.row.col.f16.f16.f16.f16 "
        "{%0,%1}, {%2,%3,%4,%5}, {%6,%7}, {%0,%1};"
        : "+r"(d[0]), "+r"(d[1])
        : "r"(a[0]), "r"(a[1]), "r"(a[2]), "r"(a[3]), "r"(b0), "r"(b1));
}
__device__ __forceinline__ float ex2(float x) {
    float r;
    asm("ex2.approx.f32 %0, %1;" : "=f"(r) : "f"(x));
    return r;
}
#define L2E 1.4426950408889634f

// ---------------------------------------------------------------------------
// Kernel 0: fp32 -> bf16 conversion of x and W.
// ---------------------------------------------------------------------------
__global__ __launch_bounds__(256) void convert_kernel(
    const float* __restrict__ x,
    const float* __restrict__ Wq, const float* __restrict__ Wk, const float* __restrict__ Wv)
{
    const int nt = gridDim.x * blockDim.x;
    const int id = blockIdx.x * blockDim.x + threadIdx.x;
#pragma unroll 1
    for (int i = id; i < (BATCH * CH * NPOS) / 4; i += nt) {
        const float4 t = ((const float4*)x)[i];
        const __nv_bfloat162 h0 = __floats2bfloat162_rn(t.x, t.y);
        const __nv_bfloat162 h1 = __floats2bfloat162_rn(t.z, t.w);
        uint2 p; p.x = *(const uint32_t*)&h0; p.y = *(const uint32_t*)&h1;
        *(uint2*)&g_xb[4 * i] = p;
    }
    const float* Ws[3] = {Wq, Wk, Wv};
#pragma unroll 1
    for (int m = 0; m < 3; m++) {
        const float* W = Ws[m];
#pragma unroll 1
        for (int i = id; i < (CH * CH) / 4; i += nt) {
            const float4 t = ((const float4*)W)[i];
            const __nv_bfloat162 h0 = __floats2bfloat162_rn(t.x, t.y);
            const __nv_bfloat162 h1 = __floats2bfloat162_rn(t.z, t.w);
            uint2 p; p.x = *(const uint32_t*)&h0; p.y = *(const uint32_t*)&h1;
            *(uint2*)&g_wb[m * CH * CH + 4 * i] = p;
        }
    }
}

// ---------------------------------------------------------------------------
// Kernel 1: QKV projection on HMMA (unchanged from R10).
// ---------------------------------------------------------------------------
#define XSTR 272u
#define WOFF 69632u
#define WSTR 528u
#define BOFF (WOFF + 135168u)
#define QKV_SMEM (BOFF + 1024u)

__global__ __launch_bounds__(256, 1) void qkv_mma_kernel(
    const float* __restrict__ bq, const float* __restrict__ bk, const float* __restrict__ bv)
{
    extern __shared__ __align__(16) char smem[];
    const uint32_t sb = s2u(smem);
    const int tid = threadIdx.x;
    const int lane = tid & 31, wid = tid >> 5;
    const int ntile = blockIdx.x * QT;
    const int b = blockIdx.y;
    const int m = blockIdx.z;

    {
        const char* xb = (const char*)g_xb + ((size_t)(b * CH) * NPOS + ntile) * 2;
#pragma unroll
        for (int it = 0; it < 16; it++) {
            const int g = tid + it * 256;
            const int row = g >> 4, off = (g & 15) * 16;
            cpa16(sb + row * XSTR + off, xb + (size_t)row * (NPOS * 2) + off);
        }
    }
    {
        const char* wb = (const char*)(g_wb + (size_t)m * CH * CH);
#pragma unroll
        for (int it = 0; it < 32; it++) {
            const int g = tid + it * 256;
            const int row = g >> 5, off = (g & 31) * 16;
            cpa16(sb + WOFF + row * WSTR + off, wb + (size_t)row * 512 + off);
        }
    }
    float* bias_s = (float*)(smem + BOFF);
    bias_s[tid] = (m == 0 ? bq : (m == 1 ? bk : bv))[tid];
    cp_commit();
    cp_wait<0>();
    __syncthreads();

    const uint32_t aRow = (lane & 7) + ((lane >> 4) & 1) * 8;
    const uint32_t aColB = wid * 32 + ((lane >> 3) & 1) * 16;
    const uint32_t aB = sb + aRow * XSTR + aColB;
    const uint32_t wB = sb + WOFF + (lane & 15) * WSTR + (lane >> 4) * 16;

    float s[32][4];
#pragma unroll
    for (int t = 0; t < 32; t++)
#pragma unroll
        for (int u = 0; u < 4; u++) s[t][u] = 0.f;

#pragma unroll 2
    for (int cs = 0; cs < 16; cs++) {
        uint32_t a[4];
        ldsm4t(a, aB + cs * (16 * XSTR));
#pragma unroll
        for (int ot = 0; ot < 16; ot++) {
            uint32_t w[4];
            ldsm4(w, wB + ot * (16 * WSTR) + cs * 32);
            mma16816(s[2 * ot + 0], a, w[0], w[2]);
            mma16816(s[2 * ot + 1], a, w[1], w[3]);
        }
    }

    const int r0 = wid * 16 + (lane >> 2);
    const size_t obase = ((size_t)b * NPOS + ntile) * CH;
    if (m < 2) {
        __nv_bfloat16* outp = (m == 0 ? g_q : g_k) + obase;
#pragma unroll
        for (int t = 0; t < 32; t++) {
            const int o0 = t * 8 + 2 * (lane & 3);
            const float b0 = bias_s[o0], b1 = bias_s[o0 + 1];
            const __nv_bfloat162 lo = __floats2bfloat162_rn(s[t][0] + b0, s[t][1] + b1);
            const __nv_bfloat162 hi = __floats2bfloat162_rn(s[t][2] + b0, s[t][3] + b1);
            *(uint32_t*)&outp[(size_t)r0 * CH + o0]       = *(const uint32_t*)&lo;
            *(uint32_t*)&outp[(size_t)(r0 + 8) * CH + o0] = *(const uint32_t*)&hi;
        }
    } else {
        __half* outp = g_v + obase;
#pragma unroll
        for (int t = 0; t < 32; t++) {
            const int o0 = t * 8 + 2 * (lane & 3);
            const float b0 = bias_s[o0], b1 = bias_s[o0 + 1];
            const __half2 lo = __floats2half2_rn(s[t][0] + b0, s[t][1] + b1);
            const __half2 hi = __floats2half2_rn(s[t][2] + b0, s[t][3] + b1);
            *(uint32_t*)&outp[(size_t)r0 * CH + o0]       = *(const uint32_t*)&lo;
            *(uint32_t*)&outp[(size_t)(r0 + 8) * CH + o0] = *(const uint32_t*)&hi;
        }
    }
}

// ---------------------------------------------------------------------------
// Kernel 2: HMMA flash attention, 3-stage K/V ring + persistent Q registers.
// Ring stage s (s=0..2) at s*STG: K tile (64 x 528) then V tile (64 x 528).
// Q is staged into stage 2's region at startup, read into registers, then
// that region becomes ring stage 2.
// ---------------------------------------------------------------------------
#define RS   528u
#define VOFS 33792u
#define STG  67584u
#define ATTN_SMEM 202752u

__global__ __launch_bounds__(256, 1) void attn_kernel(
    const float* __restrict__ x,
    const float* __restrict__ gamma,
    float* __restrict__ out)
{
    extern __shared__ __align__(16) char smem[];
    const uint32_t sb = s2u(smem);
    const int tid = threadIdx.x;
    const int lane = tid & 31, wid = tid >> 5;
    const int n0 = blockIdx.x * QT;
    const int b  = blockIdx.y;

    const char* qg = (const char*)(g_q + ((size_t)b * NPOS + n0) * CH);
    const char* kg = (const char*)(g_k + (size_t)b * NPOS * CH);
    const char* vg = (const char*)(g_v + (size_t)b * NPOS * CH);

    // ---- prologue: Q -> stage2 region (group 0); tiles 0,1 -> stages 0,1 ----
#pragma unroll
    for (int it = 0; it < 16; it++) {
        const int g = tid + it * 256;            // 4096 granules
        const int row = g >> 5, ch = g & 31;
        cpa16(sb + 2 * STG + row * RS + ch * 16, qg + row * 512 + ch * 16);
    }
    cp_commit();
#pragma unroll
    for (int st = 0; st < 2; st++) {
        const char* kgt = kg + (size_t)st * KTILE * 512;
        const char* vgt = vg + (size_t)st * KTILE * 512;
#pragma unroll
        for (int it = 0; it < 8; it++) {
            const int g = tid + it * 256;        // 2048 granules each
            const int row = g >> 5, ch = g & 31;
            cpa16(sb + st * STG + row * RS + ch * 16,        kgt + row * 512 + ch * 16);
            cpa16(sb + st * STG + VOFS + row * RS + ch * 16, vgt + row * 512 + ch * 16);
        }
        cp_commit();
    }

    // ---- Q fragments -> registers ----
    cp_wait<2>();                                // Q group complete
    __syncthreads();
    uint32_t qf[16][4];
    {
        const uint32_t aB = sb + 2 * STG + (wid * 16 + (lane & 15)) * RS + ((lane >> 4) << 4);
#pragma unroll
        for (int cs = 0; cs < 16; cs++) ldsm4(qf[cs], aB + cs * 32);
    }

    const uint32_t lrow = (lane & 15);
    const uint32_t lcol = (lane >> 4) << 4;

    // O accumulators: packed f16.
    uint32_t o2[32][2];
#pragma unroll
    for (int t = 0; t < 32; t++) { o2[t][0] = 0u; o2[t][1] = 0u; }
    float m0 = -1e30f, m1 = -1e30f, l0 = 0.f, l1 = 0.f;

    int stage = 0;
    for (int kt = 0; kt < NKT; kt++) {
        if (kt == NKT - 1) cp_wait<0>(); else cp_wait<1>();
        __syncthreads();   // tile kt visible to all; stage (kt+2)%3 fully consumed
        if (kt + 2 < NKT) {
            const int nst = (stage + 2 >= 3) ? stage - 1 : stage + 2;
            const char* kgt = kg + (size_t)(kt + 2) * KTILE * 512;
            const char* vgt = vg + (size_t)(kt + 2) * KTILE * 512;
#pragma unroll
            for (int it = 0; it < 8; it++) {
                const int g = tid + it * 256;
                const int row = g >> 5, ch = g & 31;
                cpa16(sb + nst * STG + row * RS + ch * 16,        kgt + row * 512 + ch * 16);
                cpa16(sb + nst * STG + VOFS + row * RS + ch * 16, vgt + row * 512 + ch * 16);
            }
            cp_commit();
        }

        const uint32_t kB = sb + stage * STG + lrow * RS + lcol;
        const uint32_t vB = kB + VOFS;

        // ---- S = Q K^T ----
        float s[8][4];
#pragma unroll
        for (int t = 0; t < 8; t++)
#pragma unroll
            for (int u = 0; u < 4; u++) s[t][u] = 0.f;

#pragma unroll 4
        for (int cs = 0; cs < 16; cs++) {
#pragma unroll
            for (int k16 = 0; k16 < 4; k16++) {
                uint32_t kr[4];
                ldsm4(kr, kB + k16 * (16 * RS) + cs * 32);
                mma16816(s[2 * k16 + 0], qf[cs], kr[0], kr[2]);
                mma16816(s[2 * k16 + 1], qf[cs], kr[1], kr[3]);
            }
        }

        // ---- online softmax ----
        float mt0 = s[0][0], mt1 = s[0][2];
#pragma unroll
        for (int t = 0; t < 8; t++) {
            mt0 = fmaxf(mt0, fmaxf(s[t][0], s[t][1]));
            mt1 = fmaxf(mt1, fmaxf(s[t][2], s[t][3]));
        }
        mt0 = fmaxf(mt0, __shfl_xor_sync(~0u, mt0, 1));
        mt0 = fmaxf(mt0, __shfl_xor_sync(~0u, mt0, 2));
        mt1 = fmaxf(mt1, __shfl_xor_sync(~0u, mt1, 1));
        mt1 = fmaxf(mt1, __shfl_xor_sync(~0u, mt1, 2));

        const float mn0 = fmaxf(m0, mt0), mn1 = fmaxf(m1, mt1);
        if (mn0 > m0 || mn1 > m1) {
            const float sc0 = ex2((m0 - mn0) * L2E);
            const float sc1 = ex2((m1 - mn1) * L2E);
            l0 *= sc0; l1 *= sc1;
            const __half2 sh0 = __float2half2_rn(sc0);
            const __half2 sh1 = __float2half2_rn(sc1);
#pragma unroll
            for (int t = 0; t < 32; t++) {
                __half2 u0 = *(__half2*)&o2[t][0];
                __half2 u1 = *(__half2*)&o2[t][1];
                u0 = __hmul2(u0, sh0);
                u1 = __hmul2(u1, sh1);
                o2[t][0] = *(const uint32_t*)&u0;
                o2[t][1] = *(const uint32_t*)&u1;
            }
            m0 = mn0; m1 = mn1;
        }
        const float mL0 = m0 * L2E, mL1 = m1 * L2E;
        float ps0 = 0.f, ps1 = 0.f;
#pragma unroll
        for (int t = 0; t < 8; t++) {
            s[t][0] = ex2(fmaf(s[t][0], L2E, -mL0));
            s[t][1] = ex2(fmaf(s[t][1], L2E, -mL0));
            s[t][2] = ex2(fmaf(s[t][2], L2E, -mL1));
            s[t][3] = ex2(fmaf(s[t][3], L2E, -mL1));
            ps0 += s[t][0] + s[t][1];
            ps1 += s[t][2] + s[t][3];
        }
        l0 += ps0; l1 += ps1;

        // ---- O += P V  (f16 x f16 -> f16) ----
#pragma unroll
        for (int js = 0; js < 4; js++) {
            uint32_t pa[4];
            {
                const __half2 h0 = __floats2half2_rn(s[2 * js][0], s[2 * js][1]);
                const __half2 h1 = __floats2half2_rn(s[2 * js][2], s[2 * js][3]);
                const __half2 h2 = __floats2half2_rn(s[2 * js + 1][0], s[2 * js + 1][1]);
                const __half2 h3 = __floats2half2_rn(s[2 * js + 1][2], s[2 * js + 1][3]);
                pa[0] = *(const uint32_t*)&h0;
                pa[1] = *(const uint32_t*)&h1;
                pa[2] = *(const uint32_t*)&h2;
                pa[3] = *(const uint32_t*)&h3;
            }
#pragma unroll
            for (int cp = 0; cp < 16; cp++) {
                uint32_t vr[4];
                ldsm4t(vr, vB + js * (16 * RS) + cp * 32);
                mma16816h(o2[2 * cp + 0], pa, vr[0], vr[1]);
                mma16816h(o2[2 * cp + 1], pa, vr[2], vr[3]);
            }
        }

        stage = (stage + 1 >= 3) ? 0 : stage + 1;
    }

    // ---- epilogue ----
    l0 += __shfl_xor_sync(~0u, l0, 1);
    l0 += __shfl_xor_sync(~0u, l0, 2);
    l1 += __shfl_xor_sync(~0u, l1, 1);
    l1 += __shfl_xor_sync(~0u, l1, 2);
    const float g0 = gamma[0];
    const float e0 = g0 / (l0 * 64.0f);          // sqrt(4096) = 64
    const float e1 = g0 / (l1 * 64.0f);
    const int nrow = n0 + wid * 16 + (lane >> 2);
#pragma unroll
    for (int t = 0; t < 32; t++) {
        const int c = t * 8 + 2 * (lane & 3);
        const size_t i0 = ((size_t)b * CH + c) * NPOS + nrow;
        const __half2 u0 = *(const __half2*)&o2[t][0];
        const __half2 u1 = *(const __half2*)&o2[t][1];
        out[i0]            = __low2float(u0)  * e0 + x[i0];
        out[i0 + NPOS]     = __high2float(u0) * e0 + x[i0 + NPOS];
        out[i0 + 8]        = __low2float(u1)  * e1 + x[i0 + 8];
        out[i0 + NPOS + 8] = __high2float(u1) * e1 + x[i0 + NPOS + 8];
    }
}

// ---------------------------------------------------------------------------
extern "C" void kernel_launch(void* const* d_in, const int* in_sizes, int n_in,
                              void* d_out, int out_size)
{
    const float* x     = (const float*)d_in[0];
    const float* Wq    = (const float*)d_in[1];
    const float* bq    = (const float*)d_in[2];
    const float* Wk    = (const float*)d_in[3];
    const float* bk    = (const float*)d_in[4];
    const float* Wv    = (const float*)d_in[5];
    const float* bv    = (const float*)d_in[6];
    const float* gamma = (const float*)d_in[7];
    float* out = (float*)d_out;

    cudaFuncSetAttribute(qkv_mma_kernel, cudaFuncAttributeMaxDynamicSharedMemorySize, QKV_SMEM);
    cudaFuncSetAttribute(attn_kernel,    cudaFuncAttributeMaxDynamicSharedMemorySize, ATTN_SMEM);

    convert_kernel<<<1024, 256>>>(x, Wq, Wk, Wv);
    qkv_mma_kernel<<<dim3(NPOS / QT, BATCH, 3), 256, QKV_SMEM>>>(bq, bk, bv);
    attn_kernel<<<dim3(NPOS / QT, BATCH), 256, ATTN_SMEM>>>(x, gamma, out);
}

// round 13
// speedup vs baseline: 1.0139x; 1.0139x over previous
#include <cuda_runtime.h>
#include <cuda_bf16.h>
#include <cuda_fp16.h>
#include <cstdint>

#define NPOS 4096
#define CH   256
#define BATCH 8
#define QT   128          // queries per CTA (qkv)
#define QT2  64           // queries per CTA (attn)
#define KT2  32           // keys per tile (attn)
#define NKT2 (NPOS / KT2)

// scratch
__device__ __align__(16) __nv_bfloat16 g_xb[BATCH * CH * NPOS];  // x bf16 (b,c,n)
__device__ __align__(16) __nv_bfloat16 g_wb[3 * CH * CH];        // W bf16 (m,o,c)
__device__ __align__(16) __nv_bfloat16 g_q[BATCH * NPOS * CH];   // (b,n,c)
__device__ __align__(16) __nv_bfloat16 g_k[BATCH * NPOS * CH];   // (b,n,c)
__device__ __align__(16) __half       g_v[BATCH * NPOS * CH];    // (b,n,c)  f16

// ---------------------------------------------------------------------------
// helpers
// ---------------------------------------------------------------------------
__device__ __forceinline__ uint32_t s2u(const void* p) {
    uint32_t a;
    asm("{ .reg .u64 t; cvta.to.shared.u64 t, %1; cvt.u32.u64 %0, t; }" : "=r"(a) : "l"(p));
    return a;
}
__device__ __forceinline__ void cpa16(uint32_t s, const void* g) {
    asm volatile("cp.async.cg.shared.global [%0], [%1], 16;" :: "r"(s), "l"(g));
}
__device__ __forceinline__ void cp_commit() { asm volatile("cp.async.commit_group;"); }
template <int N> __device__ __forceinline__ void cp_wait() {
    asm volatile("cp.async.wait_group %0;" :: "n"(N));
}
__device__ __forceinline__ void ldsm4(uint32_t* r, uint32_t a) {
    asm volatile("ldmatrix.sync.aligned.m8n8.x4.shared.b16 {%0,%1,%2,%3}, [%4];"
        : "=r"(r[0]), "=r"(r[1]), "=r"(r[2]), "=r"(r[3]) : "r"(a));
}
__device__ __forceinline__ void ldsm4t(uint32_t* r, uint32_t a) {
    asm volatile("ldmatrix.sync.aligned.m8n8.x4.trans.shared.b16 {%0,%1,%2,%3}, [%4];"
        : "=r"(r[0]), "=r"(r[1]), "=r"(r[2]), "=r"(r[3]) : "r"(a));
}
__device__ __forceinline__ void mma16816(float* d, const uint32_t* a, uint32_t b0, uint32_t b1) {
    asm volatile("mma.sync.aligned.m16n8k16.row.col.f32.bf16.bf16.f32 "
        "{%0,%1,%2,%3}, {%4,%5,%6,%7}, {%8,%9}, {%0,%1,%2,%3};"
        : "+f"(d[0]), "+f"(d[1]), "+f"(d[2]), "+f"(d[3])
        : "r"(a[0]), "r"(a[1]), "r"(a[2]), "r"(a[3]), "r"(b0), "r"(b1));
}
__device__ __forceinline__ void mma16816h(uint32_t* d, const uint32_t* a, uint32_t b0, uint32_t b1) {
    asm volatile("mma.sync.aligned.m16n8k16.row.col.f16.f16.f16.f16 "
        "{%0,%1}, {%2,%3,%4,%5}, {%6,%7}, {%0,%1};"
        : "+r"(d[0]), "+r"(d[1])
        : "r"(a[0]), "r"(a[1]), "r"(a[2]), "r"(a[3]), "r"(b0), "r"(b1));
}
__device__ __forceinline__ float ex2(float x) {
    float r;
    asm("ex2.approx.f32 %0, %1;" : "=f"(r) : "f"(x));
    return r;
}
#define L2E 1.4426950408889634f

// ---------------------------------------------------------------------------
// Kernel 0: fp32 -> bf16 conversion of x and W.  (unchanged from R10)
// ---------------------------------------------------------------------------
__global__ __launch_bounds__(256) void convert_kernel(
    const float* __restrict__ x,
    const float* __restrict__ Wq, const float* __restrict__ Wk, const float* __restrict__ Wv)
{
    const int nt = gridDim.x * blockDim.x;
    const int id = blockIdx.x * blockDim.x + threadIdx.x;
#pragma unroll 1
    for (int i = id; i < (BATCH * CH * NPOS) / 4; i += nt) {
        const float4 t = ((const float4*)x)[i];
        const __nv_bfloat162 h0 = __floats2bfloat162_rn(t.x, t.y);
        const __nv_bfloat162 h1 = __floats2bfloat162_rn(t.z, t.w);
        uint2 p; p.x = *(const uint32_t*)&h0; p.y = *(const uint32_t*)&h1;
        *(uint2*)&g_xb[4 * i] = p;
    }
    const float* Ws[3] = {Wq, Wk, Wv};
#pragma unroll 1
    for (int m = 0; m < 3; m++) {
        const float* W = Ws[m];
#pragma unroll 1
        for (int i = id; i < (CH * CH) / 4; i += nt) {
            const float4 t = ((const float4*)W)[i];
            const __nv_bfloat162 h0 = __floats2bfloat162_rn(t.x, t.y);
            const __nv_bfloat162 h1 = __floats2bfloat162_rn(t.z, t.w);
            uint2 p; p.x = *(const uint32_t*)&h0; p.y = *(const uint32_t*)&h1;
            *(uint2*)&g_wb[m * CH * CH + 4 * i] = p;
        }
    }
}

// ---------------------------------------------------------------------------
// Kernel 1: QKV projection on HMMA.  (unchanged from R10)
// ---------------------------------------------------------------------------
#define XSTR 272u
#define WOFF 69632u
#define WSTR 528u
#define BOFF (WOFF + 135168u)
#define QKV_SMEM (BOFF + 1024u)

__global__ __launch_bounds__(256, 1) void qkv_mma_kernel(
    const float* __restrict__ bq, const float* __restrict__ bk, const float* __restrict__ bv)
{
    extern __shared__ __align__(16) char smem[];
    const uint32_t sb = s2u(smem);
    const int tid = threadIdx.x;
    const int lane = tid & 31, wid = tid >> 5;
    const int ntile = blockIdx.x * QT;
    const int b = blockIdx.y;
    const int m = blockIdx.z;

    {
        const char* xb = (const char*)g_xb + ((size_t)(b * CH) * NPOS + ntile) * 2;
#pragma unroll
        for (int it = 0; it < 16; it++) {
            const int g = tid + it * 256;
            const int row = g >> 4, off = (g & 15) * 16;
            cpa16(sb + row * XSTR + off, xb + (size_t)row * (NPOS * 2) + off);
        }
    }
    {
        const char* wb = (const char*)(g_wb + (size_t)m * CH * CH);
#pragma unroll
        for (int it = 0; it < 32; it++) {
            const int g = tid + it * 256;
            const int row = g >> 5, off = (g & 31) * 16;
            cpa16(sb + WOFF + row * WSTR + off, wb + (size_t)row * 512 + off);
        }
    }
    float* bias_s = (float*)(smem + BOFF);
    bias_s[tid] = (m == 0 ? bq : (m == 1 ? bk : bv))[tid];
    cp_commit();
    cp_wait<0>();
    __syncthreads();

    const uint32_t aRow = (lane & 7) + ((lane >> 4) & 1) * 8;
    const uint32_t aColB = wid * 32 + ((lane >> 3) & 1) * 16;
    const uint32_t aB = sb + aRow * XSTR + aColB;
    const uint32_t wB = sb + WOFF + (lane & 15) * WSTR + (lane >> 4) * 16;

    float s[32][4];
#pragma unroll
    for (int t = 0; t < 32; t++)
#pragma unroll
        for (int u = 0; u < 4; u++) s[t][u] = 0.f;

#pragma unroll 2
    for (int cs = 0; cs < 16; cs++) {
        uint32_t a[4];
        ldsm4t(a, aB + cs * (16 * XSTR));
#pragma unroll
        for (int ot = 0; ot < 16; ot++) {
            uint32_t w[4];
            ldsm4(w, wB + ot * (16 * WSTR) + cs * 32);
            mma16816(s[2 * ot + 0], a, w[0], w[2]);
            mma16816(s[2 * ot + 1], a, w[1], w[3]);
        }
    }

    const int r0 = wid * 16 + (lane >> 2);
    const size_t obase = ((size_t)b * NPOS + ntile) * CH;
    if (m < 2) {
        __nv_bfloat16* outp = (m == 0 ? g_q : g_k) + obase;
#pragma unroll
        for (int t = 0; t < 32; t++) {
            const int o0 = t * 8 + 2 * (lane & 3);
            const float b0 = bias_s[o0], b1 = bias_s[o0 + 1];
            const __nv_bfloat162 lo = __floats2bfloat162_rn(s[t][0] + b0, s[t][1] + b1);
            const __nv_bfloat162 hi = __floats2bfloat162_rn(s[t][2] + b0, s[t][3] + b1);
            *(uint32_t*)&outp[(size_t)r0 * CH + o0]       = *(const uint32_t*)&lo;
            *(uint32_t*)&outp[(size_t)(r0 + 8) * CH + o0] = *(const uint32_t*)&hi;
        }
    } else {
        __half* outp = g_v + obase;
#pragma unroll
        for (int t = 0; t < 32; t++) {
            const int o0 = t * 8 + 2 * (lane & 3);
            const float b0 = bias_s[o0], b1 = bias_s[o0 + 1];
            const __half2 lo = __floats2half2_rn(s[t][0] + b0, s[t][1] + b1);
            const __half2 hi = __floats2half2_rn(s[t][2] + b0, s[t][3] + b1);
            *(uint32_t*)&outp[(size_t)r0 * CH + o0]       = *(const uint32_t*)&lo;
            *(uint32_t*)&outp[(size_t)(r0 + 8) * CH + o0] = *(const uint32_t*)&hi;
        }
    }
}

// ---------------------------------------------------------------------------
// Kernel 2: HMMA flash attention — R10 structure, halved CTA (QT2=64 queries,
// KT2=32-key tiles, 128 threads, 101 KB smem) -> 2 independent CTAs per SM.
// Smem: Q 64x528 = 33792; 2 buffers x (K 32x528 + V 32x528) = 2 x 33792.
// ---------------------------------------------------------------------------
#define RS    528u
#define AKO   33792u        // K/V buffers start after Q
#define AVOFS 16896u        // V offset inside a buffer
#define ASTG  33792u        // per-buffer stride
#define ATTN_SMEM (AKO + 2u * ASTG)

__global__ __launch_bounds__(128, 2) void attn_kernel(
    const float* __restrict__ x,
    const float* __restrict__ gamma,
    float* __restrict__ out)
{
    extern __shared__ __align__(16) char smem[];
    const uint32_t sb = s2u(smem);
    const int tid = threadIdx.x;
    const int lane = tid & 31, wid = tid >> 5;
    const int n0 = blockIdx.x * QT2;
    const int b  = blockIdx.y;

    const char* qg = (const char*)(g_q + ((size_t)b * NPOS + n0) * CH);
    const char* kg = (const char*)(g_k + (size_t)b * NPOS * CH);
    const char* vg = (const char*)(g_v + (size_t)b * NPOS * CH);

    // ---- preload Q (64 rows) + k/v tile 0 ----
#pragma unroll
    for (int it = 0; it < 16; it++) {
        const int g = tid + it * 128;            // 2048 granules
        const int row = g >> 5, ch = g & 31;
        cpa16(sb + row * RS + ch * 16, qg + row * 512 + ch * 16);
    }
#pragma unroll
    for (int it = 0; it < 8; it++) {
        const int g = tid + it * 128;            // 1024 granules each
        const int row = g >> 5, ch = g & 31;
        cpa16(sb + AKO + row * RS + ch * 16,         kg + row * 512 + ch * 16);
        cpa16(sb + AKO + AVOFS + row * RS + ch * 16, vg + row * 512 + ch * 16);
    }
    cp_commit();

    const uint32_t lrow = (lane & 15);
    const uint32_t lcol = (lane >> 4) << 4;
    const uint32_t aB = sb + (wid * 16 + lrow) * RS + lcol;

    // O accumulators: packed f16. o2[t][0] = row r cols {c,c+1}; o2[t][1] = row r+8.
    uint32_t o2[32][2];
#pragma unroll
    for (int t = 0; t < 32; t++) { o2[t][0] = 0u; o2[t][1] = 0u; }
    float m0 = -1e30f, m1 = -1e30f, l0 = 0.f, l1 = 0.f;

    for (int kt = 0; kt < NKT2; kt++) {
        const uint32_t buf = (kt & 1) * ASTG;
        if (kt > 0) __syncthreads();
        if (kt + 1 < NKT2) {
            const uint32_t nbuf = ((kt + 1) & 1) * ASTG;
            const char* kgt = kg + (size_t)(kt + 1) * KT2 * 512;
            const char* vgt = vg + (size_t)(kt + 1) * KT2 * 512;
#pragma unroll
            for (int it = 0; it < 8; it++) {
                const int g = tid + it * 128;
                const int row = g >> 5, ch = g & 31;
                cpa16(sb + AKO + nbuf + row * RS + ch * 16,         kgt + row * 512 + ch * 16);
                cpa16(sb + AKO + nbuf + AVOFS + row * RS + ch * 16, vgt + row * 512 + ch * 16);
            }
            cp_commit();
            cp_wait<1>();
        } else {
            cp_wait<0>();
        }
        __syncthreads();

        const uint32_t kB = sb + AKO + buf + lrow * RS + lcol;
        const uint32_t vB = kB + AVOFS;

        // ---- S = Q K^T  (16 rows x 32 keys per warp) ----
        float s[4][4];
#pragma unroll
        for (int t = 0; t < 4; t++)
#pragma unroll
            for (int u = 0; u < 4; u++) s[t][u] = 0.f;

#pragma unroll 4
        for (int cs = 0; cs < 16; cs++) {
            uint32_t a[4];
            ldsm4(a, aB + cs * 32);
#pragma unroll
            for (int k16 = 0; k16 < 2; k16++) {
                uint32_t kr[4];
                ldsm4(kr, kB + k16 * (16 * RS) + cs * 32);
                mma16816(s[2 * k16 + 0], a, kr[0], kr[2]);
                mma16816(s[2 * k16 + 1], a, kr[1], kr[3]);
            }
        }

        // ---- online softmax ----
        float mt0 = s[0][0], mt1 = s[0][2];
#pragma unroll
        for (int t = 0; t < 4; t++) {
            mt0 = fmaxf(mt0, fmaxf(s[t][0], s[t][1]));
            mt1 = fmaxf(mt1, fmaxf(s[t][2], s[t][3]));
        }
        mt0 = fmaxf(mt0, __shfl_xor_sync(~0u, mt0, 1));
        mt0 = fmaxf(mt0, __shfl_xor_sync(~0u, mt0, 2));
        mt1 = fmaxf(mt1, __shfl_xor_sync(~0u, mt1, 1));
        mt1 = fmaxf(mt1, __shfl_xor_sync(~0u, mt1, 2));

        const float mn0 = fmaxf(m0, mt0), mn1 = fmaxf(m1, mt1);
        if (mn0 > m0 || mn1 > m1) {
            const float sc0 = ex2((m0 - mn0) * L2E);
            const float sc1 = ex2((m1 - mn1) * L2E);
            l0 *= sc0; l1 *= sc1;
            const __half2 sh0 = __float2half2_rn(sc0);
            const __half2 sh1 = __float2half2_rn(sc1);
#pragma unroll
            for (int t = 0; t < 32; t++) {
                __half2 u0 = *(__half2*)&o2[t][0];
                __half2 u1 = *(__half2*)&o2[t][1];
                u0 = __hmul2(u0, sh0);
                u1 = __hmul2(u1, sh1);
                o2[t][0] = *(const uint32_t*)&u0;
                o2[t][1] = *(const uint32_t*)&u1;
            }
            m0 = mn0; m1 = mn1;
        }
        const float mL0 = m0 * L2E, mL1 = m1 * L2E;
        float ps0 = 0.f, ps1 = 0.f;
#pragma unroll
        for (int t = 0; t < 4; t++) {
            s[t][0] = ex2(fmaf(s[t][0], L2E, -mL0));
            s[t][1] = ex2(fmaf(s[t][1], L2E, -mL0));
            s[t][2] = ex2(fmaf(s[t][2], L2E, -mL1));
            s[t][3] = ex2(fmaf(s[t][3], L2E, -mL1));
            ps0 += s[t][0] + s[t][1];
            ps1 += s[t][2] + s[t][3];
        }
        l0 += ps0; l1 += ps1;

        // ---- O += P V  (f16 x f16 -> f16) ----
#pragma unroll
        for (int js = 0; js < 2; js++) {
            uint32_t pa[4];
            {
                const __half2 h0 = __floats2half2_rn(s[2 * js][0], s[2 * js][1]);
                const __half2 h1 = __floats2half2_rn(s[2 * js][2], s[2 * js][3]);
                const __half2 h2 = __floats2half2_rn(s[2 * js + 1][0], s[2 * js + 1][1]);
                const __half2 h3 = __floats2half2_rn(s[2 * js + 1][2], s[2 * js + 1][3]);
                pa[0] = *(const uint32_t*)&h0;
                pa[1] = *(const uint32_t*)&h1;
                pa[2] = *(const uint32_t*)&h2;
                pa[3] = *(const uint32_t*)&h3;
            }
#pragma unroll
            for (int cp = 0; cp < 16; cp++) {
                uint32_t vr[4];
                ldsm4t(vr, vB + js * (16 * RS) + cp * 32);
                mma16816h(o2[2 * cp + 0], pa, vr[0], vr[1]);
                mma16816h(o2[2 * cp + 1], pa, vr[2], vr[3]);
            }
        }
    }

    // ---- epilogue ----
    l0 += __shfl_xor_sync(~0u, l0, 1);
    l0 += __shfl_xor_sync(~0u, l0, 2);
    l1 += __shfl_xor_sync(~0u, l1, 1);
    l1 += __shfl_xor_sync(~0u, l1, 2);
    const float g0 = gamma[0];
    const float e0 = g0 / (l0 * 64.0f);          // sqrt(4096) = 64
    const float e1 = g0 / (l1 * 64.0f);
    const int nrow = n0 + wid * 16 + (lane >> 2);
#pragma unroll
    for (int t = 0; t < 32; t++) {
        const int c = t * 8 + 2 * (lane & 3);
        const size_t i0 = ((size_t)b * CH + c) * NPOS + nrow;
        const __half2 u0 = *(const __half2*)&o2[t][0];
        const __half2 u1 = *(const __half2*)&o2[t][1];
        out[i0]            = __low2float(u0)  * e0 + x[i0];
        out[i0 + NPOS]     = __high2float(u0) * e0 + x[i0 + NPOS];
        out[i0 + 8]        = __low2float(u1)  * e1 + x[i0 + 8];
        out[i0 + NPOS + 8] = __high2float(u1) * e1 + x[i0 + NPOS + 8];
    }
}

// ---------------------------------------------------------------------------
extern "C" void kernel_launch(void* const* d_in, const int* in_sizes, int n_in,
                              void* d_out, int out_size)
{
    const float* x     = (const float*)d_in[0];
    const float* Wq    = (const float*)d_in[1];
    const float* bq    = (const float*)d_in[2];
    const float* Wk    = (const float*)d_in[3];
    const float* bk    = (const float*)d_in[4];
    const float* Wv    = (const float*)d_in[5];
    const float* bv    = (const float*)d_in[6];
    const float* gamma = (const float*)d_in[7];
    float* out = (float*)d_out;

    cudaFuncSetAttribute(qkv_mma_kernel, cudaFuncAttributeMaxDynamicSharedMemorySize, QKV_SMEM);
    cudaFuncSetAttribute(attn_kernel,    cudaFuncAttributeMaxDynamicSharedMemorySize, ATTN_SMEM);

    convert_kernel<<<1024, 256>>>(x, Wq, Wk, Wv);
    qkv_mma_kernel<<<dim3(NPOS / QT, BATCH, 3), 256, QKV_SMEM>>>(bq, bk, bv);
    attn_kernel<<<dim3(NPOS / QT2, BATCH), 128, ATTN_SMEM>>>(x, gamma, out);
}

// round 17
// speedup vs baseline: 1.0648x; 1.0502x over previous
#include <cuda_runtime.h>
#include <cuda_bf16.h>
#include <cuda_fp16.h>
#include <cstdint>

#define NPOS 4096
#define CH   256
#define BATCH 8
#define QT   128          // queries per CTA (qkv)
#define QT2  64           // queries per CTA (attn)
#define KTILE 64          // keys per tile (attn)
#define NKT  (NPOS / KTILE)

// scratch
__device__ __align__(16) __nv_bfloat16 g_xb[BATCH * CH * NPOS];  // x bf16 (b,c,n)
__device__ __align__(16) __nv_bfloat16 g_wb[3 * CH * CH];        // W bf16 (m,o,c)
__device__ __align__(16) __nv_bfloat16 g_q[BATCH * NPOS * CH];   // (b,n,c)
__device__ __align__(16) __nv_bfloat16 g_k[BATCH * NPOS * CH];   // (b,n,c)
__device__ __align__(16) __half       g_v[BATCH * NPOS * CH];    // (b,n,c)  f16

// ---------------------------------------------------------------------------
// helpers
// ---------------------------------------------------------------------------
__device__ __forceinline__ uint32_t s2u(const void* p) {
    uint32_t a;
    asm("{ .reg .u64 t; cvta.to.shared.u64 t, %1; cvt.u32.u64 %0, t; }" : "=r"(a) : "l"(p));
    return a;
}
__device__ __forceinline__ void cpa16(uint32_t s, const void* g) {
    asm volatile("cp.async.cg.shared.global [%0], [%1], 16;" :: "r"(s), "l"(g));
}
__device__ __forceinline__ void cp_commit() { asm volatile("cp.async.commit_group;"); }
template <int N> __device__ __forceinline__ void cp_wait() {
    asm volatile("cp.async.wait_group %0;" :: "n"(N));
}
__device__ __forceinline__ void ldsm4(uint32_t* r, uint32_t a) {
    asm volatile("ldmatrix.sync.aligned.m8n8.x4.shared.b16 {%0,%1,%2,%3}, [%4];"
        : "=r"(r[0]), "=r"(r[1]), "=r"(r[2]), "=r"(r[3]) : "r"(a));
}
__device__ __forceinline__ void ldsm4t(uint32_t* r, uint32_t a) {
    asm volatile("ldmatrix.sync.aligned.m8n8.x4.trans.shared.b16 {%0,%1,%2,%3}, [%4];"
        : "=r"(r[0]), "=r"(r[1]), "=r"(r[2]), "=r"(r[3]) : "r"(a));
}
__device__ __forceinline__ void mma16816(float* d, const uint32_t* a, uint32_t b0, uint32_t b1) {
    asm volatile("mma.sync.aligned.m16n8k16.row.col.f32.bf16.bf16.f32 "
        "{%0,%1,%2,%3}, {%4,%5,%6,%7}, {%8,%9}, {%0,%1,%2,%3};"
        : "+f"(d[0]), "+f"(d[1]), "+f"(d[2]), "+f"(d[3])
        : "r"(a[0]), "r"(a[1]), "r"(a[2]), "r"(a[3]), "r"(b0), "r"(b1));
}
__device__ __forceinline__ void mma16816h(uint32_t* d, const uint32_t* a, uint32_t b0, uint32_t b1) {
    asm volatile("mma.sync.aligned.m16n8k16.row.col.f16.f16.f16.f16 "
        "{%0,%1}, {%2,%3,%4,%5}, {%6,%7}, {%0,%1};"
        : "+r"(d[0]), "+r"(d[1])
        : "r"(a[0]), "r"(a[1]), "r"(a[2]), "r"(a[3]), "r"(b0), "r"(b1));
}
__device__ __forceinline__ float ex2(float x) {
    float r;
    asm("ex2.approx.f32 %0, %1;" : "=f"(r) : "f"(x));
    return r;
}
#define L2E 1.4426950408889634f

// ---------------------------------------------------------------------------
// Kernel 0: fp32 -> bf16 conversion of x and W.  (unchanged from R10)
// ---------------------------------------------------------------------------
__global__ __launch_bounds__(256) void convert_kernel(
    const float* __restrict__ x,
    const float* __restrict__ Wq, const float* __restrict__ Wk, const float* __restrict__ Wv)
{
    const int nt = gridDim.x * blockDim.x;
    const int id = blockIdx.x * blockDim.x + threadIdx.x;
#pragma unroll 1
    for (int i = id; i < (BATCH * CH * NPOS) / 4; i += nt) {
        const float4 t = ((const float4*)x)[i];
        const __nv_bfloat162 h0 = __floats2bfloat162_rn(t.x, t.y);
        const __nv_bfloat162 h1 = __floats2bfloat162_rn(t.z, t.w);
        uint2 p; p.x = *(const uint32_t*)&h0; p.y = *(const uint32_t*)&h1;
        *(uint2*)&g_xb[4 * i] = p;
    }
    const float* Ws[3] = {Wq, Wk, Wv};
#pragma unroll 1
    for (int m = 0; m < 3; m++) {
        const float* W = Ws[m];
#pragma unroll 1
        for (int i = id; i < (CH * CH) / 4; i += nt) {
            const float4 t = ((const float4*)W)[i];
            const __nv_bfloat162 h0 = __floats2bfloat162_rn(t.x, t.y);
            const __nv_bfloat162 h1 = __floats2bfloat162_rn(t.z, t.w);
            uint2 p; p.x = *(const uint32_t*)&h0; p.y = *(const uint32_t*)&h1;
            *(uint2*)&g_wb[m * CH * CH + 4 * i] = p;
        }
    }
}

// ---------------------------------------------------------------------------
// Kernel 1: QKV projection on HMMA.  (unchanged from R10)
// ---------------------------------------------------------------------------
#define XSTR 272u
#define WOFF 69632u
#define WSTR 528u
#define BOFF (WOFF + 135168u)
#define QKV_SMEM (BOFF + 1024u)

__global__ __launch_bounds__(256, 1) void qkv_mma_kernel(
    const float* __restrict__ bq, const float* __restrict__ bk, const float* __restrict__ bv)
{
    extern __shared__ __align__(16) char smem[];
    const uint32_t sb = s2u(smem);
    const int tid = threadIdx.x;
    const int lane = tid & 31, wid = tid >> 5;
    const int ntile = blockIdx.x * QT;
    const int b = blockIdx.y;
    const int m = blockIdx.z;

    {
        const char* xb = (const char*)g_xb + ((size_t)(b * CH) * NPOS + ntile) * 2;
#pragma unroll
        for (int it = 0; it < 16; it++) {
            const int g = tid + it * 256;
            const int row = g >> 4, off = (g & 15) * 16;
            cpa16(sb + row * XSTR + off, xb + (size_t)row * (NPOS * 2) + off);
        }
    }
    {
        const char* wb = (const char*)(g_wb + (size_t)m * CH * CH);
#pragma unroll
        for (int it = 0; it < 32; it++) {
            const int g = tid + it * 256;
            const int row = g >> 5, off = (g & 31) * 16;
            cpa16(sb + WOFF + row * WSTR + off, wb + (size_t)row * 512 + off);
        }
    }
    float* bias_s = (float*)(smem + BOFF);
    bias_s[tid] = (m == 0 ? bq : (m == 1 ? bk : bv))[tid];
    cp_commit();
    cp_wait<0>();
    __syncthreads();

    const uint32_t aRow = (lane & 7) + ((lane >> 4) & 1) * 8;
    const uint32_t aColB = wid * 32 + ((lane >> 3) & 1) * 16;
    const uint32_t aB = sb + aRow * XSTR + aColB;
    const uint32_t wB = sb + WOFF + (lane & 15) * WSTR + (lane >> 4) * 16;

    float s[32][4];
#pragma unroll
    for (int t = 0; t < 32; t++)
#pragma unroll
        for (int u = 0; u < 4; u++) s[t][u] = 0.f;

#pragma unroll 2
    for (int cs = 0; cs < 16; cs++) {
        uint32_t a[4];
        ldsm4t(a, aB + cs * (16 * XSTR));
#pragma unroll
        for (int ot = 0; ot < 16; ot++) {
            uint32_t w[4];
            ldsm4(w, wB + ot * (16 * WSTR) + cs * 32);
            mma16816(s[2 * ot + 0], a, w[0], w[2]);
            mma16816(s[2 * ot + 1], a, w[1], w[3]);
        }
    }

    const int r0 = wid * 16 + (lane >> 2);
    const size_t obase = ((size_t)b * NPOS + ntile) * CH;
    if (m < 2) {
        __nv_bfloat16* outp = (m == 0 ? g_q : g_k) + obase;
#pragma unroll
        for (int t = 0; t < 32; t++) {
            const int o0 = t * 8 + 2 * (lane & 3);
            const float b0 = bias_s[o0], b1 = bias_s[o0 + 1];
            const __nv_bfloat162 lo = __floats2bfloat162_rn(s[t][0] + b0, s[t][1] + b1);
            const __nv_bfloat162 hi = __floats2bfloat162_rn(s[t][2] + b0, s[t][3] + b1);
            *(uint32_t*)&outp[(size_t)r0 * CH + o0]       = *(const uint32_t*)&lo;
            *(uint32_t*)&outp[(size_t)(r0 + 8) * CH + o0] = *(const uint32_t*)&hi;
        }
    } else {
        __half* outp = g_v + obase;
#pragma unroll
        for (int t = 0; t < 32; t++) {
            const int o0 = t * 8 + 2 * (lane & 3);
            const float b0 = bias_s[o0], b1 = bias_s[o0 + 1];
            const __half2 lo = __floats2half2_rn(s[t][0] + b0, s[t][1] + b1);
            const __half2 hi = __floats2half2_rn(s[t][2] + b0, s[t][3] + b1);
            *(uint32_t*)&outp[(size_t)r0 * CH + o0]       = *(const uint32_t*)&lo;
            *(uint32_t*)&outp[(size_t)(r0 + 8) * CH + o0] = *(const uint32_t*)&hi;
        }
    }
}

// ---------------------------------------------------------------------------
// Kernel 2: HMMA flash attention — R10 per-warp structure, half-size CTA:
// 64 queries, 4 warps, 128 threads, KTILE=64, SINGLE K/V buffer.
// Smem: Q 64x528 = 33792; K 64x528 = 33792; V 64x528 = 33792 -> 101376 B,
// 2 CTAs/SM. Cross-CTA concurrency hides load latency + softmax phases.
// ---------------------------------------------------------------------------
#define RS    528u
#define AKO   33792u
#define AVO   67584u
#define ATTN_SMEM 101376u

__global__ __launch_bounds__(128, 2) void attn_kernel(
    const float* __restrict__ x,
    const float* __restrict__ gamma,
    float* __restrict__ out)
{
    extern __shared__ __align__(16) char smem[];
    const uint32_t sb = s2u(smem);
    const int tid = threadIdx.x;
    const int lane = tid & 31, wid = tid >> 5;
    const int n0 = blockIdx.x * QT2;
    const int b  = blockIdx.y;

    const char* qg = (const char*)(g_q + ((size_t)b * NPOS + n0) * CH);
    const char* kg = (const char*)(g_k + (size_t)b * NPOS * CH);
    const char* vg = (const char*)(g_v + (size_t)b * NPOS * CH);

    // ---- preload Q (64 rows) + K/V tile 0 ----
#pragma unroll
    for (int it = 0; it < 16; it++) {
        const int g = tid + it * 128;            // 2048 granules
        const int row = g >> 5, ch = g & 31;
        cpa16(sb + row * RS + ch * 16, qg + row * 512 + ch * 16);
    }
#pragma unroll
    for (int it = 0; it < 16; it++) {
        const int g = tid + it * 128;            // 2048 granules each
        const int row = g >> 5, ch = g & 31;
        cpa16(sb + AKO + row * RS + ch * 16, kg + row * 512 + ch * 16);
        cpa16(sb + AVO + row * RS + ch * 16, vg + row * 512 + ch * 16);
    }
    cp_commit();

    const uint32_t lrow = (lane & 15);
    const uint32_t lcol = (lane >> 4) << 4;
    const uint32_t aB = sb + (wid * 16 + lrow) * RS + lcol;
    const uint32_t kB = sb + AKO + lrow * RS + lcol;
    const uint32_t vB = sb + AVO + lrow * RS + lcol;

    // O accumulators: packed f16. o2[t][0] = row r cols {c,c+1}; o2[t][1] = row r+8.
    uint32_t o2[32][2];
#pragma unroll
    for (int t = 0; t < 32; t++) { o2[t][0] = 0u; o2[t][1] = 0u; }
    float m0 = -1e30f, m1 = -1e30f, l0 = 0.f, l1 = 0.f;

    for (int kt = 0; kt < NKT; kt++) {
        cp_wait<0>();
        __syncthreads();                         // K/V tile kt visible

        // ---- S = Q K^T  (16 rows x 64 keys per warp) ----
        float s[8][4];
#pragma unroll
        for (int t = 0; t < 8; t++)
#pragma unroll
            for (int u = 0; u < 4; u++) s[t][u] = 0.f;

#pragma unroll 4
        for (int cs = 0; cs < 16; cs++) {
            uint32_t a[4];
            ldsm4(a, aB + cs * 32);
#pragma unroll
            for (int k16 = 0; k16 < 4; k16++) {
                uint32_t kr[4];
                ldsm4(kr, kB + k16 * (16 * RS) + cs * 32);
                mma16816(s[2 * k16 + 0], a, kr[0], kr[2]);
                mma16816(s[2 * k16 + 1], a, kr[1], kr[3]);
            }
        }

        // ---- online softmax ----
        float mt0 = s[0][0], mt1 = s[0][2];
#pragma unroll
        for (int t = 0; t < 8; t++) {
            mt0 = fmaxf(mt0, fmaxf(s[t][0], s[t][1]));
            mt1 = fmaxf(mt1, fmaxf(s[t][2], s[t][3]));
        }
        mt0 = fmaxf(mt0, __shfl_xor_sync(~0u, mt0, 1));
        mt0 = fmaxf(mt0, __shfl_xor_sync(~0u, mt0, 2));
        mt1 = fmaxf(mt1, __shfl_xor_sync(~0u, mt1, 1));
        mt1 = fmaxf(mt1, __shfl_xor_sync(~0u, mt1, 2));

        const float mn0 = fmaxf(m0, mt0), mn1 = fmaxf(m1, mt1);
        if (mn0 > m0 || mn1 > m1) {
            const float sc0 = ex2((m0 - mn0) * L2E);
            const float sc1 = ex2((m1 - mn1) * L2E);
            l0 *= sc0; l1 *= sc1;
            const __half2 sh0 = __float2half2_rn(sc0);
            const __half2 sh1 = __float2half2_rn(sc1);
#pragma unroll
            for (int t = 0; t < 32; t++) {
                __half2 u0 = *(__half2*)&o2[t][0];
                __half2 u1 = *(__half2*)&o2[t][1];
                u0 = __hmul2(u0, sh0);
                u1 = __hmul2(u1, sh1);
                o2[t][0] = *(const uint32_t*)&u0;
                o2[t][1] = *(const uint32_t*)&u1;
            }
            m0 = mn0; m1 = mn1;
        }
        const float mL0 = m0 * L2E, mL1 = m1 * L2E;
        float ps0 = 0.f, ps1 = 0.f;
#pragma unroll
        for (int t = 0; t < 8; t++) {
            s[t][0] = ex2(fmaf(s[t][0], L2E, -mL0));
            s[t][1] = ex2(fmaf(s[t][1], L2E, -mL0));
            s[t][2] = ex2(fmaf(s[t][2], L2E, -mL1));
            s[t][3] = ex2(fmaf(s[t][3], L2E, -mL1));
            ps0 += s[t][0] + s[t][1];
            ps1 += s[t][2] + s[t][3];
        }
        l0 += ps0; l1 += ps1;

        // ---- O += P V  (f16 x f16 -> f16) ----
#pragma unroll
        for (int js = 0; js < 4; js++) {
            uint32_t pa[4];
            {
                const __half2 h0 = __floats2half2_rn(s[2 * js][0], s[2 * js][1]);
                const __half2 h1 = __floats2half2_rn(s[2 * js][2], s[2 * js][3]);
                const __half2 h2 = __floats2half2_rn(s[2 * js + 1][0], s[2 * js + 1][1]);
                const __half2 h3 = __floats2half2_rn(s[2 * js + 1][2], s[2 * js + 1][3]);
                pa[0] = *(const uint32_t*)&h0;
                pa[1] = *(const uint32_t*)&h1;
                pa[2] = *(const uint32_t*)&h2;
                pa[3] = *(const uint32_t*)&h3;
            }
#pragma unroll
            for (int cp = 0; cp < 16; cp++) {
                uint32_t vr[4];
                ldsm4t(vr, vB + js * (16 * RS) + cp * 32);
                mma16816h(o2[2 * cp + 0], pa, vr[0], vr[1]);
                mma16816h(o2[2 * cp + 1], pa, vr[2], vr[3]);
            }
        }

        __syncthreads();                         // all reads of K/V done
        if (kt + 1 < NKT) {
            const char* kgt = kg + (size_t)(kt + 1) * KTILE * 512;
            const char* vgt = vg + (size_t)(kt + 1) * KTILE * 512;
#pragma unroll
            for (int it = 0; it < 16; it++) {
                const int g = tid + it * 128;
                const int row = g >> 5, ch = g & 31;
                cpa16(sb + AKO + row * RS + ch * 16, kgt + row * 512 + ch * 16);
                cpa16(sb + AVO + row * RS + ch * 16, vgt + row * 512 + ch * 16);
            }
            cp_commit();
        }
    }

    // ---- epilogue ----
    l0 += __shfl_xor_sync(~0u, l0, 1);
    l0 += __shfl_xor_sync(~0u, l0, 2);
    l1 += __shfl_xor_sync(~0u, l1, 1);
    l1 += __shfl_xor_sync(~0u, l1, 2);
    const float g0 = gamma[0];
    const float e0 = g0 / (l0 * 64.0f);          // sqrt(4096) = 64
    const float e1 = g0 / (l1 * 64.0f);
    const int nrow = n0 + wid * 16 + (lane >> 2);
#pragma unroll
    for (int t = 0; t < 32; t++) {
        const int c = t * 8 + 2 * (lane & 3);
        const size_t i0 = ((size_t)b * CH + c) * NPOS + nrow;
        const __half2 u0 = *(const __half2*)&o2[t][0];
        const __half2 u1 = *(const __half2*)&o2[t][1];
        out[i0]            = __low2float(u0)  * e0 + x[i0];
        out[i0 + NPOS]     = __high2float(u0) * e0 + x[i0 + NPOS];
        out[i0 + 8]        = __low2float(u1)  * e1 + x[i0 + 8];
        out[i0 + NPOS + 8] = __high2float(u1) * e1 + x[i0 + NPOS + 8];
    }
}

// ---------------------------------------------------------------------------
extern "C" void kernel_launch(void* const* d_in, const int* in_sizes, int n_in,
                              void* d_out, int out_size)
{
    const float* x     = (const float*)d_in[0];
    const float* Wq    = (const float*)d_in[1];
    const float* bq    = (const float*)d_in[2];
    const float* Wk    = (const float*)d_in[3];
    const float* bk    = (const float*)d_in[4];
    const float* Wv    = (const float*)d_in[5];
    const float* bv    = (const float*)d_in[6];
    const float* gamma = (const float*)d_in[7];
    float* out = (float*)d_out;

    cudaFuncSetAttribute(qkv_mma_kernel, cudaFuncAttributeMaxDynamicSharedMemorySize, QKV_SMEM);
    cudaFuncSetAttribute(attn_kernel,    cudaFuncAttributeMaxDynamicSharedMemorySize, ATTN_SMEM);

    convert_kernel<<<1024, 256>>>(x, Wq, Wk, Wv);
    qkv_mma_kernel<<<dim3(NPOS / QT, BATCH, 3), 256, QKV_SMEM>>>(bq, bk, bv);
    attn_kernel<<<dim3(NPOS / QT2, BATCH), 128, ATTN_SMEM>>>(x, gamma, out);
}